// round 1
// baseline (speedup 1.0000x reference)
#include <cuda_runtime.h>
#include <math.h>

#define BATCH 64
#define T 128
#define NS 32      // state dim
#define MD 8       // input dim
#define PD 16      // obs dim
#define NP 33      // padded row stride for 32-wide matrices
#define PP 17      // padded row stride for 16-wide matrices
#define QVAR 0.01f // STD_DYN^2
#define RVAR 0.01f // STD_OBS^2
#define NTHREADS 256

// Scratch for forward-pass results consumed by the backward smoother.
__device__ float g_muf [BATCH * T * NS];
__device__ float g_mup [BATCH * T * NS];
__device__ float g_Sigf[BATCH * T * NS * NS];
__device__ float g_Sigp[BATCH * T * NS * NS];

__global__ __launch_bounds__(NTHREADS, 1)
void kalman_kernel(const float* __restrict__ Y,
                   const float* __restrict__ U,
                   const float* __restrict__ A,
                   const float* __restrict__ Bm,
                   const float* __restrict__ C,
                   const float* __restrict__ mu0,
                   const float* __restrict__ Sig0,
                   float* __restrict__ out)
{
    __shared__ float sA [NS][NP];   // A_t
    __shared__ float sSig[NS][NP];  // carry Sigma (filtered fwd / smoothed bwd)
    __shared__ float sT1[NS][NP];
    __shared__ float sT2[NS][NP];
    __shared__ float sSp[NS][NP];   // Sigma_pred (also Cholesky workspace bwd)
    __shared__ float sM [NS][NP];   // IKC fwd / M=Sf A^T bwd / unsym Sig_n bwd
    __shared__ float sD [NS][NP];   // Sig_s - Sp (bwd)
    __shared__ float sJ [NS][NP];   // smoother gain
    __shared__ float sC [PD][NP];
    __shared__ float sPCt[NS][PP];  // Sig_p C^T
    __shared__ float sK [NS][PP];   // Kalman gain
    __shared__ float sS [PD][PP];   // innovation cov (Cholesky in place)
    __shared__ float sB [NS][MD];
    __shared__ float smu[NS], smup[NS], smuf[NS], smun[NS], smud[NS];
    __shared__ float sr[PD], sy[PD], su[MD], sdinv[NS];

    const int b   = blockIdx.x;
    const int tid = threadIdx.x;

    // ---- init carry: mu = mu0, Sig = Sigma0 ----
    for (int e = tid; e < NS * NS; e += NTHREADS) sSig[e >> 5][e & 31] = Sig0[e];
    if (tid < NS) smu[tid] = mu0[tid];
    __syncthreads();

    // ======================= FORWARD FILTER =======================
    for (int t = 0; t < T; ++t) {
        const float* At = A  + ((size_t)(b * T + t)) * NS * NS;
        const float* Bt = Bm + ((size_t)(b * T + t)) * NS * MD;
        const float* Ct = C  + ((size_t)(b * T + t)) * PD * NS;
        const float* yt = Y  + ((size_t)(b * T + t)) * PD;
        const float* ut = U  + ((size_t)(b * T + t)) * MD;

        for (int e = tid; e < NS * NS; e += NTHREADS) sA[e >> 5][e & 31] = At[e];
        for (int e = tid; e < PD * NS; e += NTHREADS) sC[e >> 5][e & 31] = Ct[e];
        if (tid < NS * MD)                 sB[tid >> 3][tid & 7] = Bt[tid];
        if (tid >= 128 && tid < 128 + PD)  sy[tid - 128] = yt[tid - 128];
        if (tid >= 160 && tid < 160 + MD)  su[tid - 160] = ut[tid - 160];
        __syncthreads();

        // mu_p = A mu + B u  (warp 0) ; T1 = A * Sig (all threads)
        if (tid < NS) {
            float acc = 0.f;
            #pragma unroll
            for (int k = 0; k < NS; ++k) acc += sA[tid][k] * smu[k];
            #pragma unroll
            for (int k = 0; k < MD; ++k) acc += sB[tid][k] * su[k];
            smup[tid] = acc;
        }
        for (int e = tid; e < NS * NS; e += NTHREADS) {
            int i = e >> 5, j = e & 31; float acc = 0.f;
            #pragma unroll
            for (int k = 0; k < NS; ++k) acc += sA[i][k] * sSig[k][j];
            sT1[i][j] = acc;
        }
        __syncthreads();

        // Sig_p = T1 * A^T + Q
        for (int e = tid; e < NS * NS; e += NTHREADS) {
            int i = e >> 5, j = e & 31; float acc = (i == j) ? QVAR : 0.f;
            #pragma unroll
            for (int k = 0; k < NS; ++k) acc += sT1[i][k] * sA[j][k];
            sSp[i][j] = acc;
        }
        __syncthreads();

        // store predictions to scratch; PCt = Sig_p * C^T
        {
            float* gp = g_Sigp + ((size_t)(b * T + t)) * NS * NS;
            for (int e = tid; e < NS * NS; e += NTHREADS) gp[e] = sSp[e >> 5][e & 31];
            if (tid < NS) g_mup[(size_t)(b * T + t) * NS + tid] = smup[tid];
        }
        for (int e = tid; e < NS * PD; e += NTHREADS) {
            int i = e >> 4, j = e & 15; float acc = 0.f;
            #pragma unroll
            for (int k = 0; k < NS; ++k) acc += sSp[i][k] * sC[j][k];
            sPCt[i][j] = acc;
        }
        __syncthreads();

        // S = C * PCt + R (all 256 threads) ; r = y - C mu_p (warp 2)
        {
            int i = tid >> 4, j = tid & 15; float acc = (i == j) ? RVAR : 0.f;
            #pragma unroll
            for (int k = 0; k < NS; ++k) acc += sC[i][k] * sPCt[k][j];
            sS[i][j] = acc;
        }
        if (tid >= 64 && tid < 64 + PD) {
            int i = tid - 64; float acc = sy[i];
            #pragma unroll
            for (int k = 0; k < NS; ++k) acc -= sC[i][k] * smup[k];
            sr[i] = acc;
        }
        __syncthreads();

        // symmetrize S
        float ssym = 0.5f * (sS[tid >> 4][tid & 15] + sS[tid & 15][tid >> 4]);
        __syncthreads();
        sS[tid >> 4][tid & 15] = ssym;
        __syncthreads();

        // warp 0: Cholesky(16) of S, then solve S K^T = PCt^T (32 RHS, 1 lane each)
        if (tid < 32) {
            const int i = tid;
            #pragma unroll 1
            for (int k = 0; k < PD; ++k) {
                if (i == k) sS[k][k] = sqrtf(sS[k][k]);
                __syncwarp();
                float dkk = sS[k][k];
                if (i > k && i < PD) sS[i][k] /= dkk;
                __syncwarp();
                if (i > k && i < PD) {
                    float lik = sS[i][k];
                    for (int j = k + 1; j <= i; ++j) sS[i][j] -= lik * sS[j][k];
                }
                __syncwarp();
            }
            if (i < PD) sdinv[i] = 1.0f / sS[i][i];
            __syncwarp();
            {
                float x[PD];
                const int j = i;  // RHS column = row j of K
                #pragma unroll
                for (int r2 = 0; r2 < PD; ++r2) {
                    float acc = sPCt[j][r2];
                    #pragma unroll
                    for (int k = 0; k < r2; ++k) acc -= sS[r2][k] * x[k];
                    x[r2] = acc * sdinv[r2];
                }
                #pragma unroll
                for (int r2 = PD - 1; r2 >= 0; --r2) {
                    float acc = x[r2];
                    #pragma unroll
                    for (int k = r2 + 1; k < PD; ++k) acc -= sS[k][r2] * x[k];
                    x[r2] = acc * sdinv[r2];
                }
                #pragma unroll
                for (int r2 = 0; r2 < PD; ++r2) sK[j][r2] = x[r2];
            }
        }
        __syncthreads();

        // mu_f = mu_p + K r ; IKC = I - K C  (into sM)
        if (tid < NS) {
            float acc = smup[tid];
            #pragma unroll
            for (int k = 0; k < PD; ++k) acc += sK[tid][k] * sr[k];
            smuf[tid] = acc;
        }
        for (int e = tid; e < NS * NS; e += NTHREADS) {
            int i = e >> 5, j = e & 31; float acc = (i == j) ? 1.f : 0.f;
            #pragma unroll
            for (int k = 0; k < PD; ++k) acc -= sK[i][k] * sC[k][j];
            sM[i][j] = acc;
        }
        __syncthreads();

        // T1 = IKC * Sig_p
        for (int e = tid; e < NS * NS; e += NTHREADS) {
            int i = e >> 5, j = e & 31; float acc = 0.f;
            #pragma unroll
            for (int k = 0; k < NS; ++k) acc += sM[i][k] * sSp[k][j];
            sT1[i][j] = acc;
        }
        __syncthreads();

        // Sig_f(unsym) = T1 * IKC^T + R * K K^T
        for (int e = tid; e < NS * NS; e += NTHREADS) {
            int i = e >> 5, j = e & 31; float acc = 0.f;
            #pragma unroll
            for (int k = 0; k < NS; ++k) acc += sT1[i][k] * sM[j][k];
            float acc2 = 0.f;
            #pragma unroll
            for (int k = 0; k < PD; ++k) acc2 += sK[i][k] * sK[j][k];
            sT2[i][j] = acc + RVAR * acc2;
        }
        __syncthreads();

        // symmetrize -> carry + scratch
        {
            float* gf = g_Sigf + ((size_t)(b * T + t)) * NS * NS;
            for (int e = tid; e < NS * NS; e += NTHREADS) {
                int i = e >> 5, j = e & 31;
                float v = 0.5f * (sT2[i][j] + sT2[j][i]);
                sSig[i][j] = v; gf[e] = v;
            }
            if (tid < NS) { smu[tid] = smuf[tid]; g_muf[(size_t)(b * T + t) * NS + tid] = smuf[tid]; }
        }
        __syncthreads();
    }

    // ======================= BACKWARD SMOOTHER =======================
    // carry (sSig, smu) currently holds the T-1 filtered state = smoothed state.
    {
        float* ob = out + ((size_t)(b * T + (T - 1))) * NS * (NS + 1);
        for (int e = tid; e < NS * NS; e += NTHREADS) {
            int i = e >> 5, j = e & 31;
            ob[i * (NS + 1) + 1 + j] = sSig[i][j];
        }
        if (tid < NS) ob[tid * (NS + 1)] = smu[tid];
    }
    __syncthreads();

    for (int t = T - 2; t >= 0; --t) {
        const float* At  = A      + ((size_t)(b * T + t)) * NS * NS;
        const float* gSf = g_Sigf + ((size_t)(b * T + t)) * NS * NS;
        const float* gSp = g_Sigp + ((size_t)(b * T + t + 1)) * NS * NS;
        for (int e = tid; e < NS * NS; e += NTHREADS) {
            int i = e >> 5, j = e & 31;
            sA [i][j] = At[e];
            sT2[i][j] = gSf[e];   // Sf
            sSp[i][j] = gSp[e];   // Sp(t+1)
        }
        if (tid < NS) {
            smuf[tid] = g_muf[(size_t)(b * T + t) * NS + tid];
            smup[tid] = g_mup[(size_t)(b * T + t + 1) * NS + tid];
        }
        __syncthreads();

        // M = Sf * A^T ; D = Sig_s - Sp ; mud = mu_s - mp
        for (int e = tid; e < NS * NS; e += NTHREADS) {
            int i = e >> 5, j = e & 31; float acc = 0.f;
            #pragma unroll
            for (int k = 0; k < NS; ++k) acc += sT2[i][k] * sA[j][k];
            sM[i][j] = acc;
            sD[i][j] = sSig[i][j] - sSp[i][j];
        }
        if (tid < NS) smud[tid] = smu[tid] - smup[tid];
        __syncthreads();

        // warp 0: Cholesky(32) of Sp, then solve Sp J^T = M^T (32 RHS)
        if (tid < 32) {
            const int i = tid;
            #pragma unroll 1
            for (int k = 0; k < NS; ++k) {
                if (i == k) sSp[k][k] = sqrtf(sSp[k][k]);
                __syncwarp();
                float dkk = sSp[k][k];
                if (i > k) sSp[i][k] /= dkk;
                __syncwarp();
                if (i > k) {
                    float lik = sSp[i][k];
                    for (int j = k + 1; j <= i; ++j) sSp[i][j] -= lik * sSp[j][k];
                }
                __syncwarp();
            }
            sdinv[i] = 1.0f / sSp[i][i];
            __syncwarp();
            {
                float x[NS];
                const int j = i;  // RHS column = row j of J
                #pragma unroll
                for (int r2 = 0; r2 < NS; ++r2) {
                    float acc = sM[j][r2];
                    #pragma unroll
                    for (int k = 0; k < r2; ++k) acc -= sSp[r2][k] * x[k];
                    x[r2] = acc * sdinv[r2];
                }
                #pragma unroll
                for (int r2 = NS - 1; r2 >= 0; --r2) {
                    float acc = x[r2];
                    #pragma unroll
                    for (int k = r2 + 1; k < NS; ++k) acc -= sSp[k][r2] * x[k];
                    x[r2] = acc * sdinv[r2];
                }
                #pragma unroll
                for (int r2 = 0; r2 < NS; ++r2) sJ[j][r2] = x[r2];
            }
        }
        __syncthreads();

        // mu_n = mf + J * mud ; T1 = J * D
        if (tid < NS) {
            float acc = smuf[tid];
            #pragma unroll
            for (int k = 0; k < NS; ++k) acc += sJ[tid][k] * smud[k];
            smun[tid] = acc;
        }
        for (int e = tid; e < NS * NS; e += NTHREADS) {
            int i = e >> 5, j = e & 31; float acc = 0.f;
            #pragma unroll
            for (int k = 0; k < NS; ++k) acc += sJ[i][k] * sD[k][j];
            sT1[i][j] = acc;
        }
        __syncthreads();

        // Sig_n(unsym) = Sf + T1 * J^T  (into sM)
        for (int e = tid; e < NS * NS; e += NTHREADS) {
            int i = e >> 5, j = e & 31; float acc = sT2[i][j];
            #pragma unroll
            for (int k = 0; k < NS; ++k) acc += sT1[i][k] * sJ[j][k];
            sM[i][j] = acc;
        }
        __syncthreads();

        // symmetrize -> carry + output
        {
            float* ob = out + ((size_t)(b * T + t)) * NS * (NS + 1);
            for (int e = tid; e < NS * NS; e += NTHREADS) {
                int i = e >> 5, j = e & 31;
                float v = 0.5f * (sM[i][j] + sM[j][i]);
                sSig[i][j] = v;
                ob[i * (NS + 1) + 1 + j] = v;
            }
            if (tid < NS) { smu[tid] = smun[tid]; ob[tid * (NS + 1)] = smun[tid]; }
        }
        __syncthreads();
    }
}

extern "C" void kernel_launch(void* const* d_in, const int* in_sizes, int n_in,
                              void* d_out, int out_size)
{
    const float* Y    = (const float*)d_in[0];
    const float* U    = (const float*)d_in[1];
    const float* A    = (const float*)d_in[2];
    const float* Bm   = (const float*)d_in[3];
    const float* C    = (const float*)d_in[4];
    const float* mu0  = (const float*)d_in[5];
    const float* Sig0 = (const float*)d_in[6];
    float* out = (float*)d_out;

    kalman_kernel<<<BATCH, NTHREADS>>>(Y, U, A, Bm, C, mu0, Sig0, out);
}

// round 3
// speedup vs baseline: 1.2456x; 1.2456x over previous
#include <cuda_runtime.h>
#include <math.h>

#define BATCH 64
#define T 128
#define NS 32      // state dim
#define MD 8       // input dim
#define PD 16      // obs dim
#define ST 34      // padded stride (even -> float2-aligned rows) for 32-wide
#define SP 18      // padded stride for 16-wide
#define QVAR 0.01f
#define RVAR 0.01f
#define NTH 256

// Scratch for forward-pass results consumed by the backward smoother.
__device__ float g_muf [BATCH * T * NS];
__device__ float g_mup [BATCH * T * NS];
__device__ float g_Sigf[BATCH * T * NS * NS];
__device__ float g_Sigp[BATCH * T * NS * NS];

__global__ __launch_bounds__(NTH, 1)
void kalman_kernel(const float* __restrict__ Y,
                   const float* __restrict__ U,
                   const float* __restrict__ A,
                   const float* __restrict__ Bm,
                   const float* __restrict__ C,
                   const float* __restrict__ mu0,
                   const float* __restrict__ Sig0,
                   float* __restrict__ out)
{
    __shared__ __align__(16) float sAt [NS][ST];           // A transposed: sAt[k][i] = A[i][k]
    __shared__ __align__(16) float sSig[NS][ST];           // carry (symmetric)
    __shared__ __align__(16) float sT1 [NS][ST];           // T1 transposed
    __shared__ __align__(16) float sSfA[NS][ST], sSfB[NS][ST];   // bwd Sf double buffer
    __shared__ __align__(16) float sSpA[NS][ST], sSpB[NS][ST];   // Sp (fwd uses A only) / bwd double buffer
    __shared__ __align__(16) union {
        struct { float Ct[NS][SP], PCt[NS][SP], PCtT[PD][ST], Kt[PD][ST], S[PD][SP], B[NS][MD]; } f;
        struct { float M[NS][ST], D[NS][ST], Jt[NS][ST]; } w;
    } u;
    __shared__ float smu[NS], smupF[NS], sr[PD], sy[PD], su[MD], sdinv[NS], svtmp[NS];
    __shared__ float smufB[2][NS], smupB[2][NS];
    __shared__ unsigned char mapR[136], mapC[136], mapR8[36], mapC8[36];

    const int b   = blockIdx.x;
    const int tid = threadIdx.x;
    const int tr  = tid >> 4, tc = tid & 15;

    if (tid == 0) {
        int e = 0;
        for (int r = 0; r < 16; ++r)
            for (int c = r; c < 16; ++c) { mapR[e] = (unsigned char)r; mapC[e] = (unsigned char)c; ++e; }
        e = 0;
        for (int r = 0; r < 8; ++r)
            for (int c = r; c < 8; ++c) { mapR8[e] = (unsigned char)r; mapC8[e] = (unsigned char)c; ++e; }
    }

    // ---- preload t=0 inputs + init carry ----
    {
        const size_t o = (size_t)b * T;
        const float* A0 = A  + o * NS * NS;
        const float* C0 = C  + o * PD * NS;
        const float* B0 = Bm + o * NS * MD;
        for (int e = tid; e < NS * NS; e += NTH) {
            sAt[e & 31][e >> 5] = A0[e];
            sSig[e >> 5][e & 31] = Sig0[e];
        }
        for (int e = tid; e < PD * NS; e += NTH) u.f.Ct[e & 31][e >> 5] = C0[e];
        if (tid < NS * MD) u.f.B[tid >> 3][tid & 7] = B0[tid];
        if (tid < PD) sy[tid] = Y[o * PD + tid];
        if (tid < MD) su[tid] = U[o * MD + tid];
        if (tid < NS) smu[tid] = mu0[tid];
    }
    __syncthreads();

    // ======================= FORWARD FILTER =======================
    for (int t = 0; t < T; ++t) {
        const size_t bt = (size_t)b * T + t;

        // --- phase1: T1t = (A * Sig)^T ; mu_p ---
        {
            const int i0 = 2 * tr, j0 = 2 * tc;
            float c00 = 0.f, c01 = 0.f, c10 = 0.f, c11 = 0.f;
            #pragma unroll
            for (int k = 0; k < NS; ++k) {
                float2 a  = *(const float2*)&sAt[k][i0];
                float2 bb = *(const float2*)&sSig[k][j0];
                c00 += a.x * bb.x; c01 += a.x * bb.y; c10 += a.y * bb.x; c11 += a.y * bb.y;
            }
            sT1[j0][i0] = c00; sT1[j0 + 1][i0] = c01; sT1[j0][i0 + 1] = c10; sT1[j0 + 1][i0 + 1] = c11;
            if (tid < NS) {
                float acc = 0.f;
                #pragma unroll
                for (int k = 0; k < NS; ++k) acc += sAt[k][tid] * smu[k];
                #pragma unroll
                for (int k = 0; k < MD; ++k) acc += u.f.B[tid][k] * su[k];
                smupF[tid] = acc;
            }
        }
        __syncthreads();

        // --- phase2: Sp = sym(T1 * A^T) + Q ; r = y - C mu_p ; store g_mup ---
        if (tid < 136) {
            const int i0 = 2 * mapR[tid], j0 = 2 * mapC[tid];
            float c00 = 0.f, c01 = 0.f, c10 = 0.f, c11 = 0.f;
            #pragma unroll
            for (int k = 0; k < NS; ++k) {
                float2 a  = *(const float2*)&sT1[k][i0];
                float2 bb = *(const float2*)&sAt[k][j0];
                c00 += a.x * bb.x; c01 += a.x * bb.y; c10 += a.y * bb.x; c11 += a.y * bb.y;
            }
            if (i0 == j0) { c00 += QVAR; c11 += QVAR; float av = 0.5f * (c01 + c10); c01 = av; c10 = av; }
            sSpA[i0][j0] = c00; sSpA[i0][j0 + 1] = c01; sSpA[i0 + 1][j0] = c10; sSpA[i0 + 1][j0 + 1] = c11;
            if (i0 != j0) {
                sSpA[j0][i0] = c00; sSpA[j0 + 1][i0] = c01; sSpA[j0][i0 + 1] = c10; sSpA[j0 + 1][i0 + 1] = c11;
            }
        } else if (tid >= 240) {
            const int i = tid - 240;
            float acc = sy[i];
            #pragma unroll
            for (int k = 0; k < NS; ++k) acc -= u.f.Ct[k][i] * smupF[k];
            sr[i] = acc;
        } else if (tid >= 176 && tid < 208) {
            g_mup[bt * NS + (tid - 176)] = smupF[tid - 176];
        }
        __syncthreads();

        // --- phase3: PCt = Sp * C^T (both layouts) ; store g_Sigp ---
        if (tid < 128) {
            const int i0 = 2 * (tid >> 3), j0 = 2 * (tid & 7);
            float c00 = 0.f, c01 = 0.f, c10 = 0.f, c11 = 0.f;
            #pragma unroll
            for (int k = 0; k < NS; ++k) {
                float2 a  = *(const float2*)&sSpA[k][i0];
                float2 bb = *(const float2*)&u.f.Ct[k][j0];
                c00 += a.x * bb.x; c01 += a.x * bb.y; c10 += a.y * bb.x; c11 += a.y * bb.y;
            }
            u.f.PCt[i0][j0] = c00; u.f.PCt[i0][j0 + 1] = c01;
            u.f.PCt[i0 + 1][j0] = c10; u.f.PCt[i0 + 1][j0 + 1] = c11;
            u.f.PCtT[j0][i0] = c00; u.f.PCtT[j0 + 1][i0] = c01;
            u.f.PCtT[j0][i0 + 1] = c10; u.f.PCtT[j0 + 1][i0 + 1] = c11;
        } else {
            float* gp = g_Sigp + bt * NS * NS;
            for (int e = tid - 128; e < NS * NS; e += 128) gp[e] = sSpA[e >> 5][e & 31];
        }
        __syncthreads();

        // --- phase4: S = sym(C * PCt) + R ---
        if (tid < 36) {
            const int i0 = 2 * mapR8[tid], j0 = 2 * mapC8[tid];
            float c00 = 0.f, c01 = 0.f, c10 = 0.f, c11 = 0.f;
            #pragma unroll
            for (int k = 0; k < NS; ++k) {
                float2 a  = *(const float2*)&u.f.Ct[k][i0];
                float2 bb = *(const float2*)&u.f.PCt[k][j0];
                c00 += a.x * bb.x; c01 += a.x * bb.y; c10 += a.y * bb.x; c11 += a.y * bb.y;
            }
            if (i0 == j0) { c00 += RVAR; c11 += RVAR; float av = 0.5f * (c01 + c10); c01 = av; c10 = av; }
            u.f.S[i0][j0] = c00; u.f.S[i0][j0 + 1] = c01; u.f.S[i0 + 1][j0] = c10; u.f.S[i0 + 1][j0 + 1] = c11;
            if (i0 != j0) {
                u.f.S[j0][i0] = c00; u.f.S[j0 + 1][i0] = c01; u.f.S[j0][i0 + 1] = c10; u.f.S[j0 + 1][i0 + 1] = c11;
            }
        }
        __syncthreads();

        // --- phase5: warp0 chol16 + 32-RHS solve -> Kt ; warps 1-7 prefetch t+1 ---
        if (tid < 32) {
            const int i = tid;
            #pragma unroll 1
            for (int k = 0; k < PD; ++k) {
                if (i == k) u.f.S[k][k] = sqrtf(u.f.S[k][k]);
                __syncwarp();
                float dkk = u.f.S[k][k];
                if (i > k && i < PD) u.f.S[i][k] /= dkk;
                __syncwarp();
                if (i > k && i < PD) {
                    float lik = u.f.S[i][k];
                    for (int j2 = k + 1; j2 <= i; ++j2) u.f.S[i][j2] -= lik * u.f.S[j2][k];
                }
                __syncwarp();
            }
            if (i < PD) sdinv[i] = 1.0f / u.f.S[i][i];
            __syncwarp();
            {
                float x[PD];
                #pragma unroll
                for (int r2 = 0; r2 < PD; ++r2) {
                    float acc = u.f.PCt[i][r2];
                    #pragma unroll
                    for (int k = 0; k < r2; ++k) acc -= u.f.S[r2][k] * x[k];
                    x[r2] = acc * sdinv[r2];
                }
                #pragma unroll
                for (int r2 = PD - 1; r2 >= 0; --r2) {
                    float acc = x[r2];
                    #pragma unroll
                    for (int k = r2 + 1; k < PD; ++k) acc -= u.f.S[k][r2] * x[k];
                    x[r2] = acc * sdinv[r2];
                }
                #pragma unroll
                for (int r2 = 0; r2 < PD; ++r2) u.f.Kt[r2][i] = x[r2];
            }
        } else if (t + 1 < T) {
            const size_t bt1 = bt + 1;
            const float* An = A  + bt1 * NS * NS;
            const float* Cn = C  + bt1 * PD * NS;
            const float* Bn = Bm + bt1 * NS * MD;
            const int q = tid - 32;
            for (int e = q; e < NS * NS; e += 224) sAt[e & 31][e >> 5] = An[e];
            for (int e = q; e < PD * NS; e += 224) u.f.Ct[e & 31][e >> 5] = Cn[e];
            for (int e = q; e < NS * MD; e += 224) u.f.B[e >> 3][e & 7] = Bn[e];
            if (q < PD) sy[q] = Y[bt1 * PD + q];
            else if (q < PD + MD) su[q - PD] = U[bt1 * MD + (q - PD)];
        }
        __syncthreads();

        // --- phase6: Sig_f = sym(Sp - K*PCt^T) -> carry + g_Sigf ; mu_f ---
        {
            float* gf = g_Sigf + bt * NS * NS;
            float* ob = out + bt * (size_t)(NS * (NS + 1));
            if (tid < 136) {
                const int i0 = 2 * mapR[tid], j0 = 2 * mapC[tid];
                float c00 = sSpA[i0][j0],     c01 = sSpA[i0][j0 + 1];
                float c10 = sSpA[i0 + 1][j0], c11 = sSpA[i0 + 1][j0 + 1];
                #pragma unroll
                for (int k = 0; k < PD; ++k) {
                    float2 a  = *(const float2*)&u.f.Kt[k][i0];
                    float2 bb = *(const float2*)&u.f.PCtT[k][j0];
                    c00 -= a.x * bb.x; c01 -= a.x * bb.y; c10 -= a.y * bb.x; c11 -= a.y * bb.y;
                }
                if (i0 == j0) { float av = 0.5f * (c01 + c10); c01 = av; c10 = av; }
                sSig[i0][j0] = c00; sSig[i0][j0 + 1] = c01; sSig[i0 + 1][j0] = c10; sSig[i0 + 1][j0 + 1] = c11;
                gf[i0 * NS + j0] = c00; gf[i0 * NS + j0 + 1] = c01;
                gf[(i0 + 1) * NS + j0] = c10; gf[(i0 + 1) * NS + j0 + 1] = c11;
                if (i0 != j0) {
                    sSig[j0][i0] = c00; sSig[j0 + 1][i0] = c01; sSig[j0][i0 + 1] = c10; sSig[j0 + 1][i0 + 1] = c11;
                    gf[j0 * NS + i0] = c00; gf[(j0 + 1) * NS + i0] = c01;
                    gf[j0 * NS + i0 + 1] = c10; gf[(j0 + 1) * NS + i0 + 1] = c11;
                }
                if (t == T - 1) {
                    ob[i0 * (NS + 1) + 1 + j0] = c00; ob[i0 * (NS + 1) + 2 + j0] = c01;
                    ob[(i0 + 1) * (NS + 1) + 1 + j0] = c10; ob[(i0 + 1) * (NS + 1) + 2 + j0] = c11;
                    if (i0 != j0) {
                        ob[j0 * (NS + 1) + 1 + i0] = c00; ob[(j0 + 1) * (NS + 1) + 1 + i0] = c01;
                        ob[j0 * (NS + 1) + 2 + i0] = c10; ob[(j0 + 1) * (NS + 1) + 2 + i0] = c11;
                    }
                }
            } else if (tid >= 224) {
                const int i = tid - 224;
                float acc = smupF[i];
                #pragma unroll
                for (int k = 0; k < PD; ++k) acc += u.f.Kt[k][i] * sr[k];
                smu[i] = acc;
                g_muf[bt * NS + i] = acc;
                if (t == T - 1) ob[i * (NS + 1)] = acc;
            }
        }
        __syncthreads();
    }

    // ======================= BACKWARD SMOOTHER =======================
    // preload t = T-2
    {
        const int t0 = T - 2;
        const int p0 = t0 & 1;
        float (*Sf0)[ST] = p0 ? sSfB : sSfA;
        float (*Sp0)[ST] = p0 ? sSpB : sSpA;
        const size_t bt = (size_t)b * T + t0;
        const float* An  = A      + bt * NS * NS;
        const float* Sfn = g_Sigf + bt * NS * NS;
        const float* Spn = g_Sigp + (bt + 1) * NS * NS;
        for (int e = tid; e < NS * NS; e += NTH) {
            sAt[e & 31][e >> 5] = An[e];
            Sf0[e >> 5][e & 31] = Sfn[e];
            Sp0[e >> 5][e & 31] = Spn[e];
        }
        if (tid < NS) smufB[p0][tid] = g_muf[bt * NS + tid];
        else if (tid < 2 * NS) smupB[(t0 + 1) & 1][tid - NS] = g_mup[(bt + 1) * NS + (tid - NS)];
    }
    __syncthreads();

    for (int t = T - 2; t >= 0; --t) {
        const size_t bt = (size_t)b * T + t;
        const int p = t & 1;
        float (*Sf)[ST]  = p ? sSfB : sSfA;
        float (*Sp)[ST]  = p ? sSpB : sSpA;
        float (*SfN)[ST] = p ? sSfA : sSfB;
        float (*SpN)[ST] = p ? sSpA : sSpB;
        float* ob = out + bt * (size_t)(NS * (NS + 1));

        // --- phase1: M = Sf * A^T (full) ; D = Sig_s - Sp ; mud ---
        {
            const int i0 = 2 * tr, j0 = 2 * tc;
            float c00 = 0.f, c01 = 0.f, c10 = 0.f, c11 = 0.f;
            #pragma unroll
            for (int k = 0; k < NS; ++k) {
                float2 a  = *(const float2*)&Sf[k][i0];      // Sf symmetric
                float2 bb = *(const float2*)&sAt[k][j0];
                c00 += a.x * bb.x; c01 += a.x * bb.y; c10 += a.y * bb.x; c11 += a.y * bb.y;
            }
            u.w.M[i0][j0] = c00; u.w.M[i0][j0 + 1] = c01;
            u.w.M[i0 + 1][j0] = c10; u.w.M[i0 + 1][j0 + 1] = c11;
            u.w.D[i0][j0]     = sSig[i0][j0]     - Sp[i0][j0];
            u.w.D[i0][j0 + 1] = sSig[i0][j0 + 1] - Sp[i0][j0 + 1];
            u.w.D[i0 + 1][j0] = sSig[i0 + 1][j0] - Sp[i0 + 1][j0];
            u.w.D[i0 + 1][j0 + 1] = sSig[i0 + 1][j0 + 1] - Sp[i0 + 1][j0 + 1];
            if (tid < NS) svtmp[tid] = smu[tid] - smupB[(t + 1) & 1][tid];
        }
        __syncthreads();

        // --- phase2: warp0 chol32(Sp) + 32-RHS solve -> Jt ; warps 1-7 prefetch t-1 ---
        if (tid < 32) {
            const int i = tid;
            #pragma unroll 1
            for (int k = 0; k < NS; ++k) {
                if (i == k) Sp[k][k] = sqrtf(Sp[k][k]);
                __syncwarp();
                float dkk = Sp[k][k];
                if (i > k) Sp[i][k] /= dkk;
                __syncwarp();
                if (i > k) {
                    float lik = Sp[i][k];
                    for (int j2 = k + 1; j2 <= i; ++j2) Sp[i][j2] -= lik * Sp[j2][k];
                }
                __syncwarp();
            }
            sdinv[i] = 1.0f / Sp[i][i];
            __syncwarp();
            {
                float x[NS];
                #pragma unroll
                for (int r2 = 0; r2 < NS; ++r2) {
                    float acc = u.w.M[i][r2];
                    #pragma unroll
                    for (int k = 0; k < r2; ++k) acc -= Sp[r2][k] * x[k];
                    x[r2] = acc * sdinv[r2];
                }
                #pragma unroll
                for (int r2 = NS - 1; r2 >= 0; --r2) {
                    float acc = x[r2];
                    #pragma unroll
                    for (int k = r2 + 1; k < NS; ++k) acc -= Sp[k][r2] * x[k];
                    x[r2] = acc * sdinv[r2];
                }
                #pragma unroll
                for (int r2 = 0; r2 < NS; ++r2) u.w.Jt[r2][i] = x[r2];
            }
        } else if (t > 0) {
            const int q = tid - 32;
            const size_t btm = bt - 1;
            const float* An  = A      + btm * NS * NS;
            const float* Sfn = g_Sigf + btm * NS * NS;
            const float* Spn = g_Sigp + bt * NS * NS;
            for (int e = q; e < NS * NS; e += 224) {
                sAt[e & 31][e >> 5] = An[e];
                SfN[e >> 5][e & 31] = Sfn[e];
                SpN[e >> 5][e & 31] = Spn[e];
            }
            if (q < NS) smufB[(t - 1) & 1][q] = g_muf[btm * NS + q];
            else if (q < 2 * NS) smupB[t & 1][q - NS] = g_mup[bt * NS + (q - NS)];
        }
        __syncthreads();

        // --- phase3: T1t = (J * D)^T ; mu_n ---
        {
            const int i0 = 2 * tr, j0 = 2 * tc;
            float c00 = 0.f, c01 = 0.f, c10 = 0.f, c11 = 0.f;
            #pragma unroll
            for (int k = 0; k < NS; ++k) {
                float2 a  = *(const float2*)&u.w.Jt[k][i0];
                float2 bb = *(const float2*)&u.w.D[k][j0];
                c00 += a.x * bb.x; c01 += a.x * bb.y; c10 += a.y * bb.x; c11 += a.y * bb.y;
            }
            sT1[j0][i0] = c00; sT1[j0 + 1][i0] = c01; sT1[j0][i0 + 1] = c10; sT1[j0 + 1][i0 + 1] = c11;
            if (tid < NS) {
                float acc = smufB[p][tid];
                #pragma unroll
                for (int k = 0; k < NS; ++k) acc += u.w.Jt[k][tid] * svtmp[k];
                smu[tid] = acc;
                ob[tid * (NS + 1)] = acc;
            }
        }
        __syncthreads();

        // --- phase4: Sig_n = sym(Sf + T1 * J^T) -> carry + out ---
        if (tid < 136) {
            const int i0 = 2 * mapR[tid], j0 = 2 * mapC[tid];
            float c00 = Sf[i0][j0],     c01 = Sf[i0][j0 + 1];
            float c10 = Sf[i0 + 1][j0], c11 = Sf[i0 + 1][j0 + 1];
            #pragma unroll
            for (int k = 0; k < NS; ++k) {
                float2 a  = *(const float2*)&sT1[k][i0];
                float2 bb = *(const float2*)&u.w.Jt[k][j0];
                c00 += a.x * bb.x; c01 += a.x * bb.y; c10 += a.y * bb.x; c11 += a.y * bb.y;
            }
            if (i0 == j0) { float av = 0.5f * (c01 + c10); c01 = av; c10 = av; }
            sSig[i0][j0] = c00; sSig[i0][j0 + 1] = c01; sSig[i0 + 1][j0] = c10; sSig[i0 + 1][j0 + 1] = c11;
            ob[i0 * (NS + 1) + 1 + j0] = c00; ob[i0 * (NS + 1) + 2 + j0] = c01;
            ob[(i0 + 1) * (NS + 1) + 1 + j0] = c10; ob[(i0 + 1) * (NS + 1) + 2 + j0] = c11;
            if (i0 != j0) {
                sSig[j0][i0] = c00; sSig[j0 + 1][i0] = c01; sSig[j0][i0 + 1] = c10; sSig[j0 + 1][i0 + 1] = c11;
                ob[j0 * (NS + 1) + 1 + i0] = c00; ob[(j0 + 1) * (NS + 1) + 1 + i0] = c01;
                ob[j0 * (NS + 1) + 2 + i0] = c10; ob[(j0 + 1) * (NS + 1) + 2 + i0] = c11;
            }
        }
        __syncthreads();
    }
}

extern "C" void kernel_launch(void* const* d_in, const int* in_sizes, int n_in,
                              void* d_out, int out_size)
{
    const float* Y    = (const float*)d_in[0];
    const float* U    = (const float*)d_in[1];
    const float* A    = (const float*)d_in[2];
    const float* Bm   = (const float*)d_in[3];
    const float* C    = (const float*)d_in[4];
    const float* mu0  = (const float*)d_in[5];
    const float* Sig0 = (const float*)d_in[6];
    float* out = (float*)d_out;

    kalman_kernel<<<BATCH, NTH>>>(Y, U, A, Bm, C, mu0, Sig0, out);
}

// round 4
// speedup vs baseline: 2.8095x; 2.2555x over previous
#include <cuda_runtime.h>
#include <math.h>

#define BATCH 64
#define T 128
#define NS 32      // state dim
#define MD 8       // input dim
#define PD 16      // obs dim
#define ST 34      // padded stride (even -> float2-aligned rows) for 32-wide
#define SP 18      // padded stride for 16-wide
#define QVAR 0.01f
#define RVAR 0.01f
#define NTH 256

// Scratch (forward-pass products consumed later).
__device__ __align__(16) float g_muf [BATCH * T * NS];
__device__ __align__(16) float g_mup [BATCH * T * NS];
__device__ __align__(16) float g_Sigf[BATCH * T * NS * NS];
__device__ __align__(16) float g_Sigp[BATCH * T * NS * NS];
__device__ __align__(16) float g_J   [BATCH * T * NS * NS];  // J_t stored transposed: [t][k][i] = J[i][k]

__global__ __launch_bounds__(NTH, 1)
void kalman_kernel(const float* __restrict__ Y,
                   const float* __restrict__ U,
                   const float* __restrict__ A,
                   const float* __restrict__ Bm,
                   const float* __restrict__ C,
                   const float* __restrict__ mu0,
                   const float* __restrict__ Sig0,
                   float* __restrict__ out)
{
    __shared__ __align__(16) float sAt [NS][ST];   // A transposed: sAt[k][i] = A[i][k]
    __shared__ __align__(16) float sSig[NS][ST];   // carry (symmetric)
    __shared__ __align__(16) float sT1 [NS][ST];   // transposed temp
    __shared__ __align__(16) union {
        struct { float Sp[NS][ST]; float Ct[NS][SP]; float PCt[NS][SP];
                 float PCtT[PD][ST]; float Kt[PD][ST]; float S[PD][SP]; float B[NS][MD]; } f;
        struct { float slab[8][NS][33]; } j;                        // per-warp chol workspace
        struct { float Jt[2][NS][ST]; float Sf[2][NS][ST]; float Sp[2][NS][ST]; } w;
    } u;
    __shared__ float smu[NS], smupF[NS], sr[PD], sy[PD], su[MD], sdinv[NS];
    __shared__ float smuP[2][NS], smufB[2][NS], smupB[2][NS];
    __shared__ unsigned char mapR[136], mapC[136], mapR8[36], mapC8[36];

    const int b   = blockIdx.x;
    const int tid = threadIdx.x;
    const int tr  = tid >> 4, tc = tid & 15;

    if (tid == 0) {
        int e = 0;
        for (int r = 0; r < 16; ++r)
            for (int c = r; c < 16; ++c) { mapR[e] = (unsigned char)r; mapC[e] = (unsigned char)c; ++e; }
        e = 0;
        for (int r = 0; r < 8; ++r)
            for (int c = r; c < 8; ++c) { mapR8[e] = (unsigned char)r; mapC8[e] = (unsigned char)c; ++e; }
    }

    // ---- preload t=0 inputs + init carry ----
    {
        const size_t o = (size_t)b * T;
        const float* A0 = A  + o * NS * NS;
        const float* C0 = C  + o * PD * NS;
        const float* B0 = Bm + o * NS * MD;
        for (int e = tid; e < NS * NS; e += NTH) {
            sAt[e & 31][e >> 5] = A0[e];
            sSig[e >> 5][e & 31] = Sig0[e];
        }
        for (int e = tid; e < PD * NS; e += NTH) u.f.Ct[e & 31][e >> 5] = C0[e];
        if (tid < NS * MD) u.f.B[tid >> 3][tid & 7] = B0[tid];
        if (tid < PD) sy[tid] = Y[o * PD + tid];
        if (tid < MD) su[tid] = U[o * MD + tid];
        if (tid < NS) smu[tid] = mu0[tid];
    }
    __syncthreads();

    // ======================= FORWARD FILTER =======================
    for (int t = 0; t < T; ++t) {
        const size_t bt = (size_t)b * T + t;

        // --- phase1: T1t = (A * Sig)^T ; mu_p ---
        {
            const int i0 = 2 * tr, j0 = 2 * tc;
            float c00 = 0.f, c01 = 0.f, c10 = 0.f, c11 = 0.f;
            #pragma unroll
            for (int k = 0; k < NS; ++k) {
                float2 a  = *(const float2*)&sAt[k][i0];
                float2 bb = *(const float2*)&sSig[k][j0];
                c00 += a.x * bb.x; c01 += a.x * bb.y; c10 += a.y * bb.x; c11 += a.y * bb.y;
            }
            sT1[j0][i0] = c00; sT1[j0 + 1][i0] = c01; sT1[j0][i0 + 1] = c10; sT1[j0 + 1][i0 + 1] = c11;
            if (tid < NS) {
                float acc = 0.f;
                #pragma unroll
                for (int k = 0; k < NS; ++k) acc += sAt[k][tid] * smu[k];
                #pragma unroll
                for (int k = 0; k < MD; ++k) acc += u.f.B[tid][k] * su[k];
                smupF[tid] = acc;
            }
        }
        __syncthreads();

        // --- phase2: Sp = sym(T1 * A^T) + Q ; r = y - C mu_p ; store g_mup ---
        if (tid < 136) {
            const int i0 = 2 * mapR[tid], j0 = 2 * mapC[tid];
            float c00 = 0.f, c01 = 0.f, c10 = 0.f, c11 = 0.f;
            #pragma unroll
            for (int k = 0; k < NS; ++k) {
                float2 a  = *(const float2*)&sT1[k][i0];
                float2 bb = *(const float2*)&sAt[k][j0];
                c00 += a.x * bb.x; c01 += a.x * bb.y; c10 += a.y * bb.x; c11 += a.y * bb.y;
            }
            if (i0 == j0) { c00 += QVAR; c11 += QVAR; float av = 0.5f * (c01 + c10); c01 = av; c10 = av; }
            u.f.Sp[i0][j0] = c00; u.f.Sp[i0][j0 + 1] = c01; u.f.Sp[i0 + 1][j0] = c10; u.f.Sp[i0 + 1][j0 + 1] = c11;
            if (i0 != j0) {
                u.f.Sp[j0][i0] = c00; u.f.Sp[j0 + 1][i0] = c01; u.f.Sp[j0][i0 + 1] = c10; u.f.Sp[j0 + 1][i0 + 1] = c11;
            }
        } else if (tid >= 240) {
            const int i = tid - 240;
            float acc = sy[i];
            #pragma unroll
            for (int k = 0; k < NS; ++k) acc -= u.f.Ct[k][i] * smupF[k];
            sr[i] = acc;
        } else if (tid >= 176 && tid < 208) {
            g_mup[bt * NS + (tid - 176)] = smupF[tid - 176];
        }
        __syncthreads();

        // --- phase3: PCt = Sp * C^T (both layouts) ; store g_Sigp ---
        if (tid < 128) {
            const int i0 = 2 * (tid >> 3), j0 = 2 * (tid & 7);
            float c00 = 0.f, c01 = 0.f, c10 = 0.f, c11 = 0.f;
            #pragma unroll
            for (int k = 0; k < NS; ++k) {
                float2 a  = *(const float2*)&u.f.Sp[k][i0];
                float2 bb = *(const float2*)&u.f.Ct[k][j0];
                c00 += a.x * bb.x; c01 += a.x * bb.y; c10 += a.y * bb.x; c11 += a.y * bb.y;
            }
            u.f.PCt[i0][j0] = c00; u.f.PCt[i0][j0 + 1] = c01;
            u.f.PCt[i0 + 1][j0] = c10; u.f.PCt[i0 + 1][j0 + 1] = c11;
            u.f.PCtT[j0][i0] = c00; u.f.PCtT[j0 + 1][i0] = c01;
            u.f.PCtT[j0][i0 + 1] = c10; u.f.PCtT[j0 + 1][i0 + 1] = c11;
        } else {
            float* gp = g_Sigp + bt * NS * NS;
            for (int e = tid - 128; e < NS * NS; e += 128) gp[e] = u.f.Sp[e >> 5][e & 31];
        }
        __syncthreads();

        // --- phase4: S = sym(C * PCt) + R ---
        if (tid < 36) {
            const int i0 = 2 * mapR8[tid], j0 = 2 * mapC8[tid];
            float c00 = 0.f, c01 = 0.f, c10 = 0.f, c11 = 0.f;
            #pragma unroll
            for (int k = 0; k < NS; ++k) {
                float2 a  = *(const float2*)&u.f.Ct[k][i0];
                float2 bb = *(const float2*)&u.f.PCt[k][j0];
                c00 += a.x * bb.x; c01 += a.x * bb.y; c10 += a.y * bb.x; c11 += a.y * bb.y;
            }
            if (i0 == j0) { c00 += RVAR; c11 += RVAR; float av = 0.5f * (c01 + c10); c01 = av; c10 = av; }
            u.f.S[i0][j0] = c00; u.f.S[i0][j0 + 1] = c01; u.f.S[i0 + 1][j0] = c10; u.f.S[i0 + 1][j0 + 1] = c11;
            if (i0 != j0) {
                u.f.S[j0][i0] = c00; u.f.S[j0 + 1][i0] = c01; u.f.S[j0][i0 + 1] = c10; u.f.S[j0 + 1][i0 + 1] = c11;
            }
        }
        __syncthreads();

        // --- phase5: warp0 chol16 + 32-RHS solve -> Kt ; warps 1-7 prefetch t+1 ---
        if (tid < 32) {
            const int i = tid;
            #pragma unroll 1
            for (int k = 0; k < PD; ++k) {
                float dkk = u.f.S[k][k];
                float rs  = rsqrtf(dkk);
                if (i == k) { u.f.S[k][k] = dkk * rs; sdinv[k] = rs; }
                __syncwarp();
                float rsv = sdinv[k];
                if (i > k && i < PD) u.f.S[i][k] *= rsv;
                __syncwarp();
                if (i > k && i < PD) {
                    float lik = u.f.S[i][k];
                    for (int j2 = k + 1; j2 <= i; ++j2) u.f.S[i][j2] -= lik * u.f.S[j2][k];
                }
                __syncwarp();
            }
            {
                float x[PD];
                #pragma unroll
                for (int r2 = 0; r2 < PD; ++r2) {
                    float a0 = u.f.PCt[i][r2], a1 = 0.f;
                    #pragma unroll
                    for (int k = 0; k < r2; ++k) {
                        if (k & 1) a1 += u.f.S[r2][k] * x[k];
                        else       a0 -= u.f.S[r2][k] * x[k];
                    }
                    x[r2] = (a0 - a1) * sdinv[r2];
                }
                #pragma unroll
                for (int r2 = PD - 1; r2 >= 0; --r2) {
                    float a0 = x[r2], a1 = 0.f;
                    #pragma unroll
                    for (int k = r2 + 1; k < PD; ++k) {
                        if (k & 1) a1 += u.f.S[k][r2] * x[k];
                        else       a0 -= u.f.S[k][r2] * x[k];
                    }
                    x[r2] = (a0 - a1) * sdinv[r2];
                }
                #pragma unroll
                for (int r2 = 0; r2 < PD; ++r2) u.f.Kt[r2][i] = x[r2];
            }
        } else if (t + 1 < T) {
            const size_t bt1 = bt + 1;
            const float* An = A  + bt1 * NS * NS;
            const float* Cn = C  + bt1 * PD * NS;
            const float* Bn = Bm + bt1 * NS * MD;
            const int q = tid - 32;
            for (int e = q; e < NS * NS; e += 224) sAt[e & 31][e >> 5] = An[e];
            for (int e = q; e < PD * NS; e += 224) u.f.Ct[e & 31][e >> 5] = Cn[e];
            for (int e = q; e < NS * MD; e += 224) u.f.B[e >> 3][e & 7] = Bn[e];
            if (q < PD) sy[q] = Y[bt1 * PD + q];
            else if (q < PD + MD) su[q - PD] = U[bt1 * MD + (q - PD)];
        }
        __syncthreads();

        // --- phase6: Sig_f = sym(Sp - K*PCt^T) -> carry + g_Sigf ; mu_f ---
        {
            float* gf = g_Sigf + bt * NS * NS;
            float* ob = out + bt * (size_t)(NS * (NS + 1));
            if (tid < 136) {
                const int i0 = 2 * mapR[tid], j0 = 2 * mapC[tid];
                float c00 = u.f.Sp[i0][j0],     c01 = u.f.Sp[i0][j0 + 1];
                float c10 = u.f.Sp[i0 + 1][j0], c11 = u.f.Sp[i0 + 1][j0 + 1];
                #pragma unroll
                for (int k = 0; k < PD; ++k) {
                    float2 a  = *(const float2*)&u.f.Kt[k][i0];
                    float2 bb = *(const float2*)&u.f.PCtT[k][j0];
                    c00 -= a.x * bb.x; c01 -= a.x * bb.y; c10 -= a.y * bb.x; c11 -= a.y * bb.y;
                }
                if (i0 == j0) { float av = 0.5f * (c01 + c10); c01 = av; c10 = av; }
                sSig[i0][j0] = c00; sSig[i0][j0 + 1] = c01; sSig[i0 + 1][j0] = c10; sSig[i0 + 1][j0 + 1] = c11;
                gf[i0 * NS + j0] = c00; gf[i0 * NS + j0 + 1] = c01;
                gf[(i0 + 1) * NS + j0] = c10; gf[(i0 + 1) * NS + j0 + 1] = c11;
                if (i0 != j0) {
                    sSig[j0][i0] = c00; sSig[j0 + 1][i0] = c01; sSig[j0][i0 + 1] = c10; sSig[j0 + 1][i0 + 1] = c11;
                    gf[j0 * NS + i0] = c00; gf[(j0 + 1) * NS + i0] = c01;
                    gf[j0 * NS + i0 + 1] = c10; gf[(j0 + 1) * NS + i0 + 1] = c11;
                }
                if (t == T - 1) {
                    ob[i0 * (NS + 1) + 1 + j0] = c00; ob[i0 * (NS + 1) + 2 + j0] = c01;
                    ob[(i0 + 1) * (NS + 1) + 1 + j0] = c10; ob[(i0 + 1) * (NS + 1) + 2 + j0] = c11;
                    if (i0 != j0) {
                        ob[j0 * (NS + 1) + 1 + i0] = c00; ob[(j0 + 1) * (NS + 1) + 1 + i0] = c01;
                        ob[j0 * (NS + 1) + 2 + i0] = c10; ob[(j0 + 1) * (NS + 1) + 2 + i0] = c11;
                    }
                }
            } else if (tid >= 224) {
                const int i = tid - 224;
                float acc = smupF[i];
                #pragma unroll
                for (int k = 0; k < PD; ++k) acc += u.f.Kt[k][i] * sr[k];
                smu[i] = acc;
                g_muf[bt * NS + i] = acc;
                if (t == T - 1) ob[i * (NS + 1)] = acc;
            }
        }
        __syncthreads();
    }

    // =================== J PRECOMPUTE (warp-parallel, no block barriers) ===================
    // J_t = Sigf(t) * A(t)^T * Sigp(t+1)^{-1}, for t = 0..T-2. Each warp takes every 8th t.
    {
        const int w = tid >> 5, lane = tid & 31;
        float (*sl)[33] = u.j.slab[w];
        for (int t = w; t <= T - 2; t += 8) {
            const size_t bt = (size_t)b * T + t;
            const float* Ag  = A      + bt * NS * NS;
            const float* Sfg = g_Sigf + bt * NS * NS;
            const float* Spg = g_Sigp + (bt + 1) * NS * NS;

            // stage A into slab (coalesced float4)
            #pragma unroll
            for (int e = lane; e < NS * NS / 4; e += 32) {
                float4 v = ((const float4*)Ag)[e];
                int r = (4 * e) >> 5, c = (4 * e) & 31;
                sl[r][c] = v.x; sl[r][c + 1] = v.y; sl[r][c + 2] = v.z; sl[r][c + 3] = v.w;
            }
            // Sf row 'lane' into registers
            float sf[NS];
            #pragma unroll
            for (int q = 0; q < 8; ++q) {
                float4 v = ((const float4*)(Sfg + lane * NS))[q];
                sf[4 * q] = v.x; sf[4 * q + 1] = v.y; sf[4 * q + 2] = v.z; sf[4 * q + 3] = v.w;
            }
            __syncwarp();
            // m[r] = (Sf row lane) . (A row r)   [RHS row of M = Sf*A^T]
            float m[NS];
            #pragma unroll
            for (int r = 0; r < NS; ++r) {
                float a0 = 0.f, a1 = 0.f;
                #pragma unroll
                for (int k = 0; k < NS; k += 2) {
                    a0 += sf[k]     * sl[r][k];
                    a1 += sf[k + 1] * sl[r][k + 1];
                }
                m[r] = a0 + a1;
            }
            __syncwarp();
            // stage Sp into slab (overwrite A)
            #pragma unroll
            for (int e = lane; e < NS * NS / 4; e += 32) {
                float4 v = ((const float4*)Spg)[e];
                int r = (4 * e) >> 5, c = (4 * e) & 31;
                sl[r][c] = v.x; sl[r][c + 1] = v.y; sl[r][c + 2] = v.z; sl[r][c + 3] = v.w;
            }
            __syncwarp();
            // chol32 in slab; column 32 holds 1/diag
            {
                const int i = lane;
                #pragma unroll 1
                for (int k = 0; k < NS; ++k) {
                    float dkk = sl[k][k];
                    float rs  = rsqrtf(dkk);
                    if (i == k) { sl[k][k] = dkk * rs; sl[k][32] = rs; }
                    __syncwarp();
                    float rsv = sl[k][32];
                    if (i > k) sl[i][k] *= rsv;
                    __syncwarp();
                    if (i > k) {
                        float lik = sl[i][k];
                        for (int j2 = k + 1; j2 <= i; ++j2) sl[i][j2] -= lik * sl[j2][k];
                    }
                    __syncwarp();
                }
            }
            // solve Sp * z = m  (z = J row 'lane'); L in lower slab, 1/diag in col 32
            float x[NS];
            #pragma unroll
            for (int r = 0; r < NS; ++r) {
                float a0 = m[r], a1 = 0.f;
                #pragma unroll
                for (int k = 0; k < r; ++k) {
                    if (k & 1) a1 += sl[r][k] * x[k];
                    else       a0 -= sl[r][k] * x[k];
                }
                x[r] = (a0 - a1) * sl[r][32];
            }
            #pragma unroll
            for (int r = NS - 1; r >= 0; --r) {
                float a0 = x[r], a1 = 0.f;
                #pragma unroll
                for (int k = r + 1; k < NS; ++k) {
                    if (k & 1) a1 += sl[k][r] * x[k];
                    else       a0 -= sl[k][r] * x[k];
                }
                x[r] = (a0 - a1) * sl[r][32];
            }
            // store J transposed: g_J[t][k][i] = J[i][k] = x[k]  (coalesced over lanes)
            float* Jg = g_J + bt * NS * NS;
            #pragma unroll
            for (int k = 0; k < NS; ++k) Jg[k * NS + lane] = x[k];
            __syncwarp();
        }
    }
    __syncthreads();

    // =================== BACKWARD SMOOTHER (2 phases / step) ===================
    // carry: sSig = Sigf(T-1) (smoothed), smuP[(T-1)&1] = muf(T-1)
    {
        const int t0 = T - 2;
        const int p0 = t0 & 1;
        const size_t bt = (size_t)b * T + t0;
        const float* Sfg = g_Sigf + bt * NS * NS;
        const float* Spg = g_Sigp + (bt + 1) * NS * NS;
        const float* Jg  = g_J    + bt * NS * NS;
        for (int e = tid; e < NS * NS; e += NTH) {
            u.w.Sf[p0][e >> 5][e & 31] = Sfg[e];
            u.w.Sp[p0][e >> 5][e & 31] = Spg[e];
            u.w.Jt[p0][e >> 5][e & 31] = Jg[e];
        }
        if (tid < NS) { smufB[p0][tid] = g_muf[bt * NS + tid]; smuP[(T - 1) & 1][tid] = smu[tid]; }
        else if (tid < 2 * NS) smupB[p0][tid - NS] = g_mup[(bt + 1) * NS + (tid - NS)];
    }
    __syncthreads();

    for (int t = T - 2; t >= 0; --t) {
        const size_t bt = (size_t)b * T + t;
        const int p = t & 1;
        float (*Jt)[ST] = u.w.Jt[p];
        float (*Sf)[ST] = u.w.Sf[p];
        float (*Sp)[ST] = u.w.Sp[p];
        float* ob = out + bt * (size_t)(NS * (NS + 1));

        // --- phaseA: T1t = (J * (Sig_s - Sp))^T  [256 tiles, D folded] ---
        {
            const int i0 = 2 * tr, j0 = 2 * tc;
            float c00 = 0.f, c01 = 0.f, c10 = 0.f, c11 = 0.f;
            #pragma unroll
            for (int k = 0; k < NS; ++k) {
                float2 a  = *(const float2*)&Jt[k][i0];
                float2 s1 = *(const float2*)&sSig[k][j0];
                float2 s2 = *(const float2*)&Sp[k][j0];
                float bx = s1.x - s2.x, by = s1.y - s2.y;
                c00 += a.x * bx; c01 += a.x * by; c10 += a.y * bx; c11 += a.y * by;
            }
            sT1[j0][i0] = c00; sT1[j0 + 1][i0] = c01; sT1[j0][i0 + 1] = c10; sT1[j0 + 1][i0 + 1] = c11;
        }
        __syncthreads();

        // --- phaseB: Sig_n = sym(Sf + T1*J^T) [136] ; mu_n [32] ; prefetch t-1 [88] ---
        if (tid < 136) {
            const int i0 = 2 * mapR[tid], j0 = 2 * mapC[tid];
            float c00 = Sf[i0][j0],     c01 = Sf[i0][j0 + 1];
            float c10 = Sf[i0 + 1][j0], c11 = Sf[i0 + 1][j0 + 1];
            #pragma unroll
            for (int k = 0; k < NS; ++k) {
                float2 a  = *(const float2*)&sT1[k][i0];
                float2 bb = *(const float2*)&Jt[k][j0];
                c00 += a.x * bb.x; c01 += a.x * bb.y; c10 += a.y * bb.x; c11 += a.y * bb.y;
            }
            if (i0 == j0) { float av = 0.5f * (c01 + c10); c01 = av; c10 = av; }
            sSig[i0][j0] = c00; sSig[i0][j0 + 1] = c01; sSig[i0 + 1][j0] = c10; sSig[i0 + 1][j0 + 1] = c11;
            ob[i0 * (NS + 1) + 1 + j0] = c00; ob[i0 * (NS + 1) + 2 + j0] = c01;
            ob[(i0 + 1) * (NS + 1) + 1 + j0] = c10; ob[(i0 + 1) * (NS + 1) + 2 + j0] = c11;
            if (i0 != j0) {
                sSig[j0][i0] = c00; sSig[j0 + 1][i0] = c01; sSig[j0][i0 + 1] = c10; sSig[j0 + 1][i0 + 1] = c11;
                ob[j0 * (NS + 1) + 1 + i0] = c00; ob[(j0 + 1) * (NS + 1) + 1 + i0] = c01;
                ob[j0 * (NS + 1) + 2 + i0] = c10; ob[(j0 + 1) * (NS + 1) + 2 + i0] = c11;
            }
        } else if (tid < 168) {
            const int i = tid - 136;
            float acc = smufB[p][i];
            #pragma unroll
            for (int k = 0; k < NS; ++k) acc += Jt[k][i] * (smuP[p ^ 1][k] - smupB[p][k]);
            smuP[p][i] = acc;
            ob[i * (NS + 1)] = acc;
        } else if (t > 0) {
            const int q = tid - 168;
            const size_t btm = bt - 1;
            const float* Sfg = g_Sigf + btm * NS * NS;
            const float* Spg = g_Sigp + bt * NS * NS;
            const float* Jg  = g_J    + btm * NS * NS;
            const int pn = p ^ 1;
            for (int e = q; e < NS * NS; e += 88) {
                u.w.Sf[pn][e >> 5][e & 31] = Sfg[e];
                u.w.Sp[pn][e >> 5][e & 31] = Spg[e];
                u.w.Jt[pn][e >> 5][e & 31] = Jg[e];
            }
            if (q < NS) smufB[pn][q] = g_muf[btm * NS + q];
            else if (q < 2 * NS) smupB[pn][q - NS] = g_mup[bt * NS + (q - NS)];
        }
        __syncthreads();
    }
}

extern "C" void kernel_launch(void* const* d_in, const int* in_sizes, int n_in,
                              void* d_out, int out_size)
{
    const float* Y    = (const float*)d_in[0];
    const float* U    = (const float*)d_in[1];
    const float* A    = (const float*)d_in[2];
    const float* Bm   = (const float*)d_in[3];
    const float* C    = (const float*)d_in[4];
    const float* mu0  = (const float*)d_in[5];
    const float* Sig0 = (const float*)d_in[6];
    float* out = (float*)d_out;

    kalman_kernel<<<BATCH, NTH>>>(Y, U, A, Bm, C, mu0, Sig0, out);
}